// round 10
// baseline (speedup 1.0000x reference)
#include <cuda_runtime.h>
#include <cstdint>

#define NT     128
#define ETILE  96                       // 6 x m16 blocks
#define HID    128
#define SROW   512                      // bytes per edge-row, 32 chunks of 16B, XOR-swizzled
#define ZBUF   (ETILE * SROW)           // 49152 B per buffer
#define OFF_BW  0                       // b1[128] + W2[128] floats = 1024 B
#define OFF_PRT 1024                    // 96 edges * 4 cgroups * 4B = 1536 B
#define OFF_Z   2560
#define SMEM_BYTES (OFF_Z + 2 * ZBUF)   // 100864 B -> 2 CTAs/SM (201.7 of 228 KB)

#define NS_U 6400000                    // student table in uint32 (fp16 pairs)
#define NC_U 1280000
__device__ uint32_t g_zh[NS_U + NC_U];  // fp16 tables scratch (31 MB)

// ---------------- helpers ----------------
__device__ __forceinline__ uint32_t smem_u32(const void* p) {
    uint32_t a;
    asm("{ .reg .u64 t; cvta.to.shared.u64 t, %1; cvt.u32.u64 %0, t; }" : "=r"(a) : "l"(p));
    return a;
}
__device__ __forceinline__ uint32_t hfpair(float lo, float hi) {
    uint32_t r;
    asm("cvt.rn.f16x2.f32 %0, %1, %2;" : "=r"(r) : "f"(hi), "f"(lo));
    return r;
}
__device__ __forceinline__ void ldmat4(uint32_t (&r)[4], uint32_t addr) {
    asm volatile("ldmatrix.sync.aligned.m8n8.x4.shared.b16 {%0,%1,%2,%3}, [%4];"
                 : "=r"(r[0]), "=r"(r[1]), "=r"(r[2]), "=r"(r[3]) : "r"(addr));
}
__device__ __forceinline__ void mma16816(float (&d)[4], const uint32_t (&a)[4],
                                         uint32_t b0, uint32_t b1) {
    asm volatile("mma.sync.aligned.m16n8k16.row.col.f32.f16.f16.f32 "
                 "{%0,%1,%2,%3}, {%4,%5,%6,%7}, {%8,%9}, {%0,%1,%2,%3};"
                 : "+f"(d[0]), "+f"(d[1]), "+f"(d[2]), "+f"(d[3])
                 : "r"(a[0]), "r"(a[1]), "r"(a[2]), "r"(a[3]), "r"(b0), "r"(b1));
}
#define CP_ASYNC16(dst, src) \
    asm volatile("cp.async.cg.shared.global [%0], [%1], 16;" :: "r"(dst), "l"(src) : "memory")
#define CP_COMMIT() asm volatile("cp.async.commit_group;" ::: "memory")
#define CP_WAIT(n)  asm volatile("cp.async.wait_group %0;" :: "n"(n) : "memory")

// ---------------- table convert: fp32 -> fp16 pairs (run each call) ----------------
__global__ void cvt_tables(const float* __restrict__ zs, const float* __restrict__ zc) {
    const int total = NS_U + NC_U;
    for (int i = blockIdx.x * blockDim.x + threadIdx.x; i < total;
         i += gridDim.x * blockDim.x) {
        const float* src = (i < NS_U) ? (zs + 2 * (size_t)i)
                                      : (zc + 2 * (size_t)(i - NS_U));
        g_zh[i] = hfpair(src[0], src[1]);
    }
}

// ---------------- gather via cp.async: 8 threads/edge, 6 passes of 16 edges ----------------
__device__ __forceinline__ void gather_async(const int* __restrict__ row,
                                             const int* __restrict__ col,
                                             int base, int E, int tid, uint32_t zdst) {
    const int q = tid & 7;
    #pragma unroll
    for (int pass = 0; pass < 6; pass++) {
        const int e_t = (tid >> 3) + pass * 16;
        const int eg  = base + e_t;
        const int ri  = (eg < E) ? row[eg] : 0;
        const int ci  = (eg < E) ? col[eg] : 0;
        const char* su = (const char*)(g_zh + (size_t)ri * 64);
        const char* cu = (const char*)(g_zh + NS_U + (size_t)ci * 64);
        const uint32_t rowp = zdst + (uint32_t)e_t * SROW;
        #pragma unroll
        for (int j = 0; j < 4; j++) {
            const int c  = 8 * j + q;                   // chunk 0..31
            const int cs = (c & 24) | ((c ^ e_t) & 7);  // XOR swizzle
            const char* src = (j < 2) ? (su + (c & 15) * 16) : (cu + (c & 15) * 16);
            CP_ASYNC16(rowp + cs * 16, src);
        }
    }
}

// ---------------- kernel ----------------
__global__ void __launch_bounds__(NT, 2)
edge_decoder_mma(const int* __restrict__ row, const int* __restrict__ col,
                 const float* __restrict__ W1, const float* __restrict__ b1,
                 const float* __restrict__ W2, const float* __restrict__ b2,
                 float* __restrict__ out, int E)
{
    extern __shared__ __align__(16) char sm[];
    float* sB1 = (float*)(sm + OFF_BW);        // [128]
    float* sW2 = sB1 + HID;                    // [128]
    float* prt = (float*)(sm + OFF_PRT);       // [96 edges][4 cgroups]
    char*  zsm = sm + OFF_Z;

    const int tid  = threadIdx.x;
    const int lane = tid & 31;
    const int wid  = tid >> 5;    // cgroup 0..3
    const int tq   = lane & 3;
    const int tr   = lane >> 2;
    const int wcol = wid * 32;

    // stage b1/W2 into smem (frees 16 regs vs register-resident epilogue consts)
    if (tid < HID) { sB1[tid] = b1[tid]; sW2[tid] = W2[tid]; }
    const float b2v = b2[0];

    // ---- B = W1 fragments, fp16, register-resident (128 regs) ----
    uint32_t B[4][16][2];
    #pragma unroll
    for (int nb = 0; nb < 4; nb++) {
        const int n = wcol + nb * 8 + tr;
        #pragma unroll
        for (int s = 0; s < 16; s++) {
            #pragma unroll
            for (int hh = 0; hh < 2; hh++) {
                const int k0 = s * 16 + tq * 2 + hh * 8;
                B[nb][s][hh] = hfpair(W1[(size_t)k0 * HID + n],
                                      W1[(size_t)(k0 + 1) * HID + n]);
            }
        }
    }

    const uint32_t zb0 = smem_u32(zsm);
    const int r0  = lane & 15;
    const int hh0 = lane >> 4;

    const int numTiles = (E + ETILE - 1) / ETILE;
    int t = blockIdx.x;
    int buf = 0;

    if (t < numTiles) {
        gather_async(row, col, t * ETILE, E, tid, zb0);
        CP_COMMIT();
    }

    while (t < numTiles) {
        const int tn = t + gridDim.x;

        // issue next tile's gather into other buffer, then wait for current
        if (tn < numTiles) {
            gather_async(row, col, tn * ETILE, E, tid, zb0 + (uint32_t)(buf ^ 1) * ZBUF);
            CP_COMMIT();
            CP_WAIT(1);
        } else {
            CP_WAIT(0);
        }
        __syncthreads();   // buf visible; prt consumed; sB1/sW2 visible (first iter)

        // ---- MMA mainloop: mb=6 (in 3 pairs) x nb=4, 16 k-steps ----
        float D[6][4][4];
        #pragma unroll
        for (int mb = 0; mb < 6; mb++)
            #pragma unroll
            for (int nb = 0; nb < 4; nb++)
                #pragma unroll
                for (int i = 0; i < 4; i++) D[mb][nb][i] = 0.f;

        const uint32_t zb = zb0 + (uint32_t)buf * ZBUF;
        #pragma unroll
        for (int s = 0; s < 16; s++) {
            const int c  = 2 * s + hh0;
            #pragma unroll
            for (int mp = 0; mp < 3; mp++) {          // mb pairs keep A live-range at 8 regs
                uint32_t A[2][4];
                #pragma unroll
                for (int i = 0; i < 2; i++) {
                    const int r  = (mp * 2 + i) * 16 + r0;
                    const int cs = (c & 24) | ((c ^ r) & 7);
                    ldmat4(A[i], zb + (uint32_t)(r * SROW + cs * 16));
                }
                #pragma unroll
                for (int i = 0; i < 2; i++)
                    #pragma unroll
                    for (int nb = 0; nb < 4; nb++)
                        mma16816(D[mp * 2 + i][nb], A[i], B[nb][s][0], B[nb][s][1]);
            }
        }

        // ---- epilogue: bias + ReLU + W2 (consts from smem), quad-reduce, stash ----
        #pragma unroll
        for (int mb = 0; mb < 6; mb++) {
            float s0 = 0.f, s1 = 0.f;
            #pragma unroll
            for (int nb = 0; nb < 4; nb++) {
                const int c0 = wcol + nb * 8 + tq * 2;
                const float bb0 = sB1[c0],  bb1 = sB1[c0 + 1];
                const float ww0 = sW2[c0],  ww1 = sW2[c0 + 1];
                s0 += fmaxf(D[mb][nb][0] + bb0, 0.f) * ww0;
                s0 += fmaxf(D[mb][nb][1] + bb1, 0.f) * ww1;
                s1 += fmaxf(D[mb][nb][2] + bb0, 0.f) * ww0;
                s1 += fmaxf(D[mb][nb][3] + bb1, 0.f) * ww1;
            }
            s0 += __shfl_xor_sync(0xffffffffu, s0, 1);
            s0 += __shfl_xor_sync(0xffffffffu, s0, 2);
            s1 += __shfl_xor_sync(0xffffffffu, s1, 1);
            s1 += __shfl_xor_sync(0xffffffffu, s1, 2);
            if (tq == 0) {
                int ebase = mb * 16 + tr;
                prt[ebase * 4 + wid]       = s0;
                prt[(ebase + 8) * 4 + wid] = s1;
            }
        }
        __syncthreads();
        if (tid < ETILE) {
            float4 p = ((const float4*)prt)[tid];
            float o = p.x + p.y + p.z + p.w + b2v;
            int eg = t * ETILE + tid;
            if (eg < E) out[eg] = o;
        }

        t = tn;
        buf ^= 1;
    }
}

extern "C" void kernel_launch(void* const* d_in, const int* in_sizes, int n_in,
                              void* d_out, int out_size)
{
    const float* zs  = (const float*)d_in[0];
    const float* zc  = (const float*)d_in[1];
    const int*   row = (const int*)d_in[2];
    const int*   col = (const int*)d_in[3];
    const float* W1  = (const float*)d_in[4];
    const float* b1  = (const float*)d_in[5];
    const float* W2  = (const float*)d_in[6];
    const float* b2  = (const float*)d_in[7];
    float* out = (float*)d_out;
    const int E = in_sizes[2];

    static bool attr_set = false;  // idempotent, not a work guard
    if (!attr_set) {
        cudaFuncSetAttribute(edge_decoder_mma,
                             cudaFuncAttributeMaxDynamicSharedMemorySize, SMEM_BYTES);
        attr_set = true;
    }

    int sms = 148;
    cudaDeviceGetAttribute(&sms, cudaDevAttrMultiProcessorCount, 0);

    // 1) convert embedding tables to fp16 scratch (deterministic, every call)
    cvt_tables<<<4 * sms, 256>>>(zs, zc);

    // 2) main fused gather + MMA kernel: 2 CTAs per SM, phase-decoupled
    int numTiles = (E + ETILE - 1) / ETILE;
    int grid = 2 * sms;
    if (grid > numTiles) grid = numTiles;
    edge_decoder_mma<<<grid, NT, SMEM_BYTES>>>(row, col, W1, b1, W2, b2, out, E);
}

// round 11
// speedup vs baseline: 1.8410x; 1.8410x over previous
#include <cuda_runtime.h>
#include <cuda_fp16.h>
#include <cstdint>

#define HID    128
// capacities (problem shape: 100000 students, 20000 courses, 128 features)
#define NS_CAP 100096
#define NC_CAP 20096
__device__ uint32_t g_zh[(NS_CAP + NC_CAP) * 64];  // fp16 z tables (as f16x2 words)
__device__ uint32_t g_h [(NS_CAP + NC_CAP) * 64];  // fp16 h_pre tables

// ---------------- helpers ----------------
__device__ __forceinline__ uint32_t smem_u32(const void* p) {
    uint32_t a;
    asm("{ .reg .u64 t; cvta.to.shared.u64 t, %1; cvt.u32.u64 %0, t; }" : "=r"(a) : "l"(p));
    return a;
}
__device__ __forceinline__ uint32_t hfpair(float lo, float hi) {
    uint32_t r;
    asm("cvt.rn.f16x2.f32 %0, %1, %2;" : "=r"(r) : "f"(hi), "f"(lo));
    return r;
}
__device__ __forceinline__ void ldmat4(uint32_t (&r)[4], uint32_t addr) {
    asm volatile("ldmatrix.sync.aligned.m8n8.x4.shared.b16 {%0,%1,%2,%3}, [%4];"
                 : "=r"(r[0]), "=r"(r[1]), "=r"(r[2]), "=r"(r[3]) : "r"(addr));
}
__device__ __forceinline__ void mma16816(float (&d)[4], const uint32_t (&a)[4],
                                         uint32_t b0, uint32_t b1) {
    asm volatile("mma.sync.aligned.m16n8k16.row.col.f32.f16.f16.f32 "
                 "{%0,%1,%2,%3}, {%4,%5,%6,%7}, {%8,%9}, {%0,%1,%2,%3};"
                 : "+f"(d[0]), "+f"(d[1]), "+f"(d[2]), "+f"(d[3])
                 : "r"(a[0]), "r"(a[1]), "r"(a[2]), "r"(a[3]), "r"(b0), "r"(b1));
}
#define CP_ASYNC16(dst, src) \
    asm volatile("cp.async.cg.shared.global [%0], [%1], 16;" :: "r"(dst), "l"(src) : "memory")
#define CP_COMMIT() asm volatile("cp.async.commit_group;" ::: "memory")
#define CP_WAIT0()  asm volatile("cp.async.wait_group 0;" ::: "memory")

// ---------------- 1) table convert: fp32 -> fp16 pairs ----------------
__global__ void cvt_tables(const float* __restrict__ zs, const float* __restrict__ zc,
                           int nsU, int ncU) {
    const int total = nsU + ncU;
    for (int i = blockIdx.x * blockDim.x + threadIdx.x; i < total;
         i += gridDim.x * blockDim.x) {
        const float* src = (i < nsU) ? (zs + 2 * (size_t)i)
                                     : (zc + 2 * (size_t)(i - nsU));
        g_zh[i] = hfpair(src[0], src[1]);
    }
}

// ---------------- 2) node GEMM: h = z @ W1_half, fp16 out (no bias) ----------------
// One CTA per 64-row tile. A = 64x128 fp16 in smem (rows contiguous in gmem).
#define GROWS 64
#define SR2   256   // bytes per A row (128 fp16), 16 chunks of 16B
__global__ void __launch_bounds__(128)
gemm_pre(const float* __restrict__ W1, int nsTiles, int nS, int nC, int nsU) {
    __shared__ __align__(16) char sA[GROWS * SR2];   // 16 KB

    const int tile = blockIdx.x;
    const bool isC = tile >= nsTiles;
    const int rbase = (isC ? tile - nsTiles : tile) * GROWS;
    const int nrows = isC ? nC : nS;
    const uint32_t* ztab = g_zh + (isC ? (size_t)nsU : 0);
    uint32_t*       htab = g_h  + (isC ? (size_t)nsU : 0);
    const int kofs = isC ? HID : 0;     // which half of W1

    const int tid  = threadIdx.x;
    const int lane = tid & 31;
    const int wid  = tid >> 5;
    const int tq   = lane & 3;
    const int tr   = lane >> 2;
    const int wcol = wid * 32;

    // B = W1 half fragments (8 k-steps, 64 regs)
    uint32_t B[4][8][2];
    #pragma unroll
    for (int nb = 0; nb < 4; nb++) {
        const int n = wcol + nb * 8 + tr;
        #pragma unroll
        for (int s = 0; s < 8; s++)
            #pragma unroll
            for (int hh = 0; hh < 2; hh++) {
                const int k0 = kofs + s * 16 + tq * 2 + hh * 8;
                B[nb][s][hh] = hfpair(W1[(size_t)k0 * HID + n],
                                      W1[(size_t)(k0 + 1) * HID + n]);
            }
    }

    // A tile via cp.async (contiguous rows, XOR-swizzled)
    const uint32_t ab = smem_u32(sA);
    {
        const int q  = tid & 15;            // chunk
        const int rr = tid >> 4;            // 8 rows per pass
        #pragma unroll
        for (int pass = 0; pass < 8; pass++) {
            int rloc = rr + pass * 8;
            int rg   = rbase + rloc; if (rg >= nrows) rg = nrows - 1;
            const char* src = (const char*)(ztab + (size_t)rg * 64) + q * 16;
            const int cs = (q & 8) | ((q ^ rloc) & 7);
            CP_ASYNC16(ab + rloc * SR2 + cs * 16, src);
        }
        CP_COMMIT();
        CP_WAIT0();
    }
    __syncthreads();

    // mainloop: mb=4, nb=4, 8 k-steps
    float D[4][4][4];
    #pragma unroll
    for (int mb = 0; mb < 4; mb++)
        #pragma unroll
        for (int nb = 0; nb < 4; nb++)
            #pragma unroll
            for (int i = 0; i < 4; i++) D[mb][nb][i] = 0.f;

    const int r0  = lane & 15;
    const int hh0 = lane >> 4;
    #pragma unroll
    for (int s = 0; s < 8; s++) {
        const int c = 2 * s + hh0;
        uint32_t A[4][4];
        #pragma unroll
        for (int mb = 0; mb < 4; mb++) {
            const int r  = mb * 16 + r0;
            const int cs = (c & 8) | ((c ^ r) & 7);
            ldmat4(A[mb], ab + (uint32_t)(r * SR2 + cs * 16));
        }
        #pragma unroll
        for (int mb = 0; mb < 4; mb++)
            #pragma unroll
            for (int nb = 0; nb < 4; nb++)
                mma16816(D[mb][nb], A[mb], B[nb][s][0], B[nb][s][1]);
    }

    // store h as fp16 pairs
    #pragma unroll
    for (int mb = 0; mb < 4; mb++)
        #pragma unroll
        for (int nb = 0; nb < 4; nb++) {
            const int cp = (wcol >> 1) + nb * 4 + tq;   // col-pair index 0..63
            const int r1 = rbase + mb * 16 + tr;
            const int r2 = r1 + 8;
            if (r1 < nrows) htab[(size_t)r1 * 64 + cp] = hfpair(D[mb][nb][0], D[mb][nb][1]);
            if (r2 < nrows) htab[(size_t)r2 * 64 + cp] = hfpair(D[mb][nb][2], D[mb][nb][3]);
        }
}

// ---------------- 3) edge pass: out = relu(h_s[row]+h_c[col]+b1) . W2 + b2 ----------------
__global__ void __launch_bounds__(256)
edge_out(const int* __restrict__ row, const int* __restrict__ col,
         const float* __restrict__ b1f, const float* __restrict__ W2f,
         const float* __restrict__ b2f, float* __restrict__ out, int E, int nsU) {
    const int tid = threadIdx.x;
    const int q   = tid & 7;           // 8 threads per edge

    // this thread's 16 columns: {8q..8q+7} and {64+8q..64+8q+7}
    __half2 b1h[8];
    float   w2[16];
    #pragma unroll
    for (int j = 0; j < 4; j++) {
        const int c = 8 * q + 2 * j;
        b1h[j]     = __floats2half2_rn(b1f[c],      b1f[c + 1]);
        b1h[4 + j] = __floats2half2_rn(b1f[64 + c], b1f[64 + c + 1]);
    }
    #pragma unroll
    for (int j = 0; j < 8; j++) {
        w2[j]     = W2f[8 * q + j];
        w2[8 + j] = W2f[64 + 8 * q + j];
    }
    const float b2v = b2f[0];
    const __half2 zero = __float2half2_rn(0.f);
    const uint32_t* hS = g_h;
    const uint32_t* hC = g_h + (size_t)nsU;

    const int slot  = (blockIdx.x * blockDim.x + tid) >> 3;
    const int nslot = (gridDim.x * blockDim.x) >> 3;

    for (int eg = slot; eg < E; eg += nslot) {
        const int ri = row[eg];
        const int ci = col[eg];
        const uint4* hs = (const uint4*)(hS + (size_t)ri * 64);
        const uint4* hc = (const uint4*)(hC + (size_t)ci * 64);
        uint4 s0 = hs[q], s1 = hs[q + 8];
        uint4 c0 = hc[q], c1 = hc[q + 8];

        float acc = 0.f;
        const uint32_t* su0 = &s0.x; const uint32_t* cu0 = &c0.x;
        const uint32_t* su1 = &s1.x; const uint32_t* cu1 = &c1.x;
        #pragma unroll
        for (int i = 0; i < 4; i++) {
            __half2 h = __hmax2(__hadd2(__hadd2(*(const __half2*)&su0[i],
                                                *(const __half2*)&cu0[i]), b1h[i]), zero);
            float2 f = __half22float2(h);
            acc = fmaf(f.x, w2[2 * i], acc);
            acc = fmaf(f.y, w2[2 * i + 1], acc);
        }
        #pragma unroll
        for (int i = 0; i < 4; i++) {
            __half2 h = __hmax2(__hadd2(__hadd2(*(const __half2*)&su1[i],
                                                *(const __half2*)&cu1[i]), b1h[4 + i]), zero);
            float2 f = __half22float2(h);
            acc = fmaf(f.x, w2[8 + 2 * i], acc);
            acc = fmaf(f.y, w2[8 + 2 * i + 1], acc);
        }
        acc += __shfl_xor_sync(0xffffffffu, acc, 1);
        acc += __shfl_xor_sync(0xffffffffu, acc, 2);
        acc += __shfl_xor_sync(0xffffffffu, acc, 4);
        if (q == 0) out[eg] = acc + b2v;
    }
}

extern "C" void kernel_launch(void* const* d_in, const int* in_sizes, int n_in,
                              void* d_out, int out_size)
{
    const float* zs  = (const float*)d_in[0];
    const float* zc  = (const float*)d_in[1];
    const int*   row = (const int*)d_in[2];
    const int*   col = (const int*)d_in[3];
    const float* W1  = (const float*)d_in[4];
    const float* b1  = (const float*)d_in[5];
    const float* W2  = (const float*)d_in[6];
    const float* b2  = (const float*)d_in[7];
    float* out = (float*)d_out;

    const int E  = in_sizes[2];
    const int nS = in_sizes[0] / HID;
    const int nC = in_sizes[1] / HID;
    const int nsU = nS * 64;   // u32 words per student table
    const int ncU = nC * 64;

    int sms = 148;
    cudaDeviceGetAttribute(&sms, cudaDevAttrMultiProcessorCount, 0);

    // 1) fp16 copies of z tables
    cvt_tables<<<4 * sms, 256>>>(zs, zc, nsU, ncU);

    // 2) per-node GEMM: h_s = zs @ W1_top, h_c = zc @ W1_bot
    const int nsTiles = (nS + GROWS - 1) / GROWS;
    const int ncTiles = (nC + GROWS - 1) / GROWS;
    gemm_pre<<<nsTiles + ncTiles, 128>>>(W1, nsTiles, nS, nC, nsU);

    // 3) edge pass
    edge_out<<<8 * sms, 256>>>(row, col, b1, W2, b2, out, E, nsU);
}

// round 12
// speedup vs baseline: 2.5850x; 1.4041x over previous
#include <cuda_runtime.h>
#include <cuda_fp16.h>
#include <cstdint>

#define HID    128
#define NS_CAP 100096
#define NC_CAP 20096
__device__ uint32_t g_h[(NS_CAP + NC_CAP) * 64];  // fp16 h tables (f16x2 words)

// ---------------- helpers ----------------
__device__ __forceinline__ uint32_t smem_u32(const void* p) {
    uint32_t a;
    asm("{ .reg .u64 t; cvta.to.shared.u64 t, %1; cvt.u32.u64 %0, t; }" : "=r"(a) : "l"(p));
    return a;
}
__device__ __forceinline__ uint32_t hfpair(float lo, float hi) {
    uint32_t r;
    asm("cvt.rn.f16x2.f32 %0, %1, %2;" : "=r"(r) : "f"(hi), "f"(lo));
    return r;
}
__device__ __forceinline__ void ldmat4(uint32_t (&r)[4], uint32_t addr) {
    asm volatile("ldmatrix.sync.aligned.m8n8.x4.shared.b16 {%0,%1,%2,%3}, [%4];"
                 : "=r"(r[0]), "=r"(r[1]), "=r"(r[2]), "=r"(r[3]) : "r"(addr));
}
__device__ __forceinline__ void mma16816(float (&d)[4], const uint32_t (&a)[4],
                                         uint32_t b0, uint32_t b1) {
    asm volatile("mma.sync.aligned.m16n8k16.row.col.f32.f16.f16.f32 "
                 "{%0,%1,%2,%3}, {%4,%5,%6,%7}, {%8,%9}, {%0,%1,%2,%3};"
                 : "+f"(d[0]), "+f"(d[1]), "+f"(d[2]), "+f"(d[3])
                 : "r"(a[0]), "r"(a[1]), "r"(a[2]), "r"(a[3]), "r"(b0), "r"(b1));
}

// ---------------- 1) node GEMM: h = fp16(z) @ fp16(W1_half), fp16 out ----------------
// One CTA per 64-row tile; A loaded as fp32 from the input tensor, converted in regs.
#define GROWS 64
#define SR2   256   // bytes per A row (128 fp16), 16 chunks of 16B
__global__ void __launch_bounds__(128)
gemm_pre(const float* __restrict__ zs, const float* __restrict__ zc,
         const float* __restrict__ W1, int nsTiles, int nS, int nC, int nsU) {
    __shared__ __align__(16) char sA[GROWS * SR2];   // 16 KB

    const int tile = blockIdx.x;
    const bool isC = tile >= nsTiles;
    const int rbase = (isC ? tile - nsTiles : tile) * GROWS;
    const int nrows = isC ? nC : nS;
    const float* ztab = isC ? zc : zs;
    uint32_t*    htab = g_h + (isC ? (size_t)nsU : 0);
    const int kofs = isC ? HID : 0;

    const int tid  = threadIdx.x;
    const int lane = tid & 31;
    const int wid  = tid >> 5;
    const int tq   = lane & 3;
    const int tr   = lane >> 2;
    const int wcol = wid * 32;

    // A: fp32 LDG.128 (coalesced) -> cvt -> swizzled fp16 STS (overlaps B-frag build)
    const uint32_t ab = smem_u32(sA);
    #pragma unroll
    for (int p = 0; p < 16; p++) {                 // 2048 float4 / 128 threads
        const int i  = tid + p * 128;
        const int r  = i >> 5;                     // 32 float4 per row
        const int f4 = i & 31;
        int rg = rbase + r; if (rg >= nrows) rg = nrows - 1;
        const float4 v = ((const float4*)(ztab + (size_t)rg * HID))[f4];
        const uint32_t h0 = hfpair(v.x, v.y), h1 = hfpair(v.z, v.w);
        const int c = f4 >> 1, hf = f4 & 1;
        const int cs = (c & 8) | ((c ^ r) & 7);
        *(uint2*)(sA + r * SR2 + cs * 16 + hf * 8) = make_uint2(h0, h1);
    }

    // B = W1 half fragments (8 k-steps, 64 regs)
    uint32_t B[4][8][2];
    #pragma unroll
    for (int nb = 0; nb < 4; nb++) {
        const int n = wcol + nb * 8 + tr;
        #pragma unroll
        for (int s = 0; s < 8; s++)
            #pragma unroll
            for (int hh = 0; hh < 2; hh++) {
                const int k0 = kofs + s * 16 + tq * 2 + hh * 8;
                B[nb][s][hh] = hfpair(W1[(size_t)k0 * HID + n],
                                      W1[(size_t)(k0 + 1) * HID + n]);
            }
    }
    __syncthreads();

    float D[4][4][4];
    #pragma unroll
    for (int mb = 0; mb < 4; mb++)
        #pragma unroll
        for (int nb = 0; nb < 4; nb++)
            #pragma unroll
            for (int i = 0; i < 4; i++) D[mb][nb][i] = 0.f;

    const int r0  = lane & 15;
    const int hh0 = lane >> 4;
    #pragma unroll
    for (int s = 0; s < 8; s++) {
        const int c = 2 * s + hh0;
        uint32_t A[4][4];
        #pragma unroll
        for (int mb = 0; mb < 4; mb++) {
            const int r  = mb * 16 + r0;
            const int cs = (c & 8) | ((c ^ r) & 7);
            ldmat4(A[mb], ab + (uint32_t)(r * SR2 + cs * 16));
        }
        #pragma unroll
        for (int mb = 0; mb < 4; mb++)
            #pragma unroll
            for (int nb = 0; nb < 4; nb++)
                mma16816(D[mb][nb], A[mb], B[nb][s][0], B[nb][s][1]);
    }

    #pragma unroll
    for (int mb = 0; mb < 4; mb++)
        #pragma unroll
        for (int nb = 0; nb < 4; nb++) {
            const int cp = (wcol >> 1) + nb * 4 + tq;
            const int r1 = rbase + mb * 16 + tr;
            const int r2 = r1 + 8;
            if (r1 < nrows) htab[(size_t)r1 * 64 + cp] = hfpair(D[mb][nb][0], D[mb][nb][1]);
            if (r2 < nrows) htab[(size_t)r2 * 64 + cp] = hfpair(D[mb][nb][2], D[mb][nb][3]);
        }
}

// ---------------- 2) edge pass, unroll x2: out = relu(h_s+h_c+b1).W2 + b2 ----------------
__global__ void __launch_bounds__(256)
edge_out(const int* __restrict__ row, const int* __restrict__ col,
         const float* __restrict__ b1f, const float* __restrict__ W2f,
         const float* __restrict__ b2f, float* __restrict__ out, int E, int nsU) {
    const int tid = threadIdx.x;
    const int q   = tid & 7;

    __half2 b1h[8];
    float   w2[16];
    #pragma unroll
    for (int j = 0; j < 4; j++) {
        const int c = 8 * q + 2 * j;
        b1h[j]     = __floats2half2_rn(b1f[c],      b1f[c + 1]);
        b1h[4 + j] = __floats2half2_rn(b1f[64 + c], b1f[64 + c + 1]);
    }
    #pragma unroll
    for (int j = 0; j < 8; j++) {
        w2[j]     = W2f[8 * q + j];
        w2[8 + j] = W2f[64 + 8 * q + j];
    }
    const float b2v = b2f[0];
    const __half2 zero = __float2half2_rn(0.f);
    const uint32_t* hS = g_h;
    const uint32_t* hC = g_h + (size_t)nsU;

    const int slot  = (blockIdx.x * blockDim.x + tid) >> 3;
    const int nslot = (gridDim.x * blockDim.x) >> 3;

    for (int eg = slot; eg < E; eg += 2 * nslot) {
        const int eg2   = eg + nslot;
        const bool has2 = eg2 < E;

        const int ri  = row[eg];
        const int ci  = col[eg];
        const int ri2 = has2 ? row[eg2] : ri;
        const int ci2 = has2 ? col[eg2] : ci;

        const uint4* hs  = (const uint4*)(hS + (size_t)ri  * 64);
        const uint4* hc  = (const uint4*)(hC + (size_t)ci  * 64);
        const uint4* hs2 = (const uint4*)(hS + (size_t)ri2 * 64);
        const uint4* hc2 = (const uint4*)(hC + (size_t)ci2 * 64);
        uint4 a0 = hs[q],  a1 = hs[q + 8],  b0 = hc[q],  b1u = hc[q + 8];
        uint4 c0 = hs2[q], c1 = hs2[q + 8], d0 = hc2[q], d1 = hc2[q + 8];

        float acc1 = 0.f, acc2 = 0.f;
        const uint32_t* pa0 = &a0.x; const uint32_t* pb0 = &b0.x;
        const uint32_t* pa1 = &a1.x; const uint32_t* pb1 = &b1u.x;
        const uint32_t* pc0 = &c0.x; const uint32_t* pd0 = &d0.x;
        const uint32_t* pc1 = &c1.x; const uint32_t* pd1 = &d1.x;
        #pragma unroll
        for (int i = 0; i < 4; i++) {
            __half2 h1 = __hmax2(__hadd2(__hadd2(*(const __half2*)&pa0[i],
                                                 *(const __half2*)&pb0[i]), b1h[i]), zero);
            __half2 h2 = __hmax2(__hadd2(__hadd2(*(const __half2*)&pa1[i],
                                                 *(const __half2*)&pb1[i]), b1h[4 + i]), zero);
            float2 f1 = __half22float2(h1);
            float2 f2 = __half22float2(h2);
            acc1 = fmaf(f1.x, w2[2 * i], acc1);
            acc1 = fmaf(f1.y, w2[2 * i + 1], acc1);
            acc1 = fmaf(f2.x, w2[8 + 2 * i], acc1);
            acc1 = fmaf(f2.y, w2[8 + 2 * i + 1], acc1);

            __half2 g1 = __hmax2(__hadd2(__hadd2(*(const __half2*)&pc0[i],
                                                 *(const __half2*)&pd0[i]), b1h[i]), zero);
            __half2 g2 = __hmax2(__hadd2(__hadd2(*(const __half2*)&pc1[i],
                                                 *(const __half2*)&pd1[i]), b1h[4 + i]), zero);
            float2 e1 = __half22float2(g1);
            float2 e2 = __half22float2(g2);
            acc2 = fmaf(e1.x, w2[2 * i], acc2);
            acc2 = fmaf(e1.y, w2[2 * i + 1], acc2);
            acc2 = fmaf(e2.x, w2[8 + 2 * i], acc2);
            acc2 = fmaf(e2.y, w2[8 + 2 * i + 1], acc2);
        }
        #pragma unroll
        for (int m = 1; m <= 4; m <<= 1) {
            acc1 += __shfl_xor_sync(0xffffffffu, acc1, m);
            acc2 += __shfl_xor_sync(0xffffffffu, acc2, m);
        }
        if (q == 0) {
            out[eg] = acc1 + b2v;
            if (has2) out[eg2] = acc2 + b2v;
        }
    }
}

extern "C" void kernel_launch(void* const* d_in, const int* in_sizes, int n_in,
                              void* d_out, int out_size)
{
    const float* zs  = (const float*)d_in[0];
    const float* zc  = (const float*)d_in[1];
    const int*   row = (const int*)d_in[2];
    const int*   col = (const int*)d_in[3];
    const float* W1  = (const float*)d_in[4];
    const float* b1  = (const float*)d_in[5];
    const float* W2  = (const float*)d_in[6];
    const float* b2  = (const float*)d_in[7];
    float* out = (float*)d_out;

    const int E  = in_sizes[2];
    const int nS = in_sizes[0] / HID;
    const int nC = in_sizes[1] / HID;
    const int nsU = nS * 64;

    int sms = 148;
    cudaDeviceGetAttribute(&sms, cudaDevAttrMultiProcessorCount, 0);

    // 1) per-node GEMM with fused fp32->fp16 A-load
    const int nsTiles = (nS + GROWS - 1) / GROWS;
    const int ncTiles = (nC + GROWS - 1) / GROWS;
    gemm_pre<<<nsTiles + ncTiles, 128>>>(zs, zc, W1, nsTiles, nS, nC, nsU);

    // 2) edge pass
    edge_out<<<8 * sms, 256>>>(row, col, b1, W2, b2, out, E, nsU);
}

// round 13
// speedup vs baseline: 2.9264x; 1.1321x over previous
#include <cuda_runtime.h>
#include <cuda_fp16.h>
#include <cstdint>

#define HID    128
#define NS_CAP 100096
#define NC_CAP 20096
__device__ uint32_t g_h[(NS_CAP + NC_CAP) * 64];  // fp16 h tables (f16x2 words)

// ---------------- helpers ----------------
__device__ __forceinline__ uint32_t smem_u32(const void* p) {
    uint32_t a;
    asm("{ .reg .u64 t; cvta.to.shared.u64 t, %1; cvt.u32.u64 %0, t; }" : "=r"(a) : "l"(p));
    return a;
}
__device__ __forceinline__ uint32_t hfpair(float lo, float hi) {
    uint32_t r;
    asm("cvt.rn.f16x2.f32 %0, %1, %2;" : "=r"(r) : "f"(hi), "f"(lo));
    return r;
}
__device__ __forceinline__ void ldmat4(uint32_t (&r)[4], uint32_t addr) {
    asm volatile("ldmatrix.sync.aligned.m8n8.x4.shared.b16 {%0,%1,%2,%3}, [%4];"
                 : "=r"(r[0]), "=r"(r[1]), "=r"(r[2]), "=r"(r[3]) : "r"(addr));
}
__device__ __forceinline__ void mma16816(float (&d)[4], const uint32_t (&a)[4],
                                         uint32_t b0, uint32_t b1) {
    asm volatile("mma.sync.aligned.m16n8k16.row.col.f32.f16.f16.f32 "
                 "{%0,%1,%2,%3}, {%4,%5,%6,%7}, {%8,%9}, {%0,%1,%2,%3};"
                 : "+f"(d[0]), "+f"(d[1]), "+f"(d[2]), "+f"(d[3])
                 : "r"(a[0]), "r"(a[1]), "r"(a[2]), "r"(a[3]), "r"(b0), "r"(b1));
}

// ---------------- 1) persistent node GEMM: h = fp16(z) @ fp16(W1_half) ----------------
#define GROWS 64
#define SR2   256   // bytes per A row (128 fp16), 16 chunks of 16B
__global__ void __launch_bounds__(128)
gemm_pre(const float* __restrict__ zs, const float* __restrict__ zc,
         const float* __restrict__ W1, int nS, int nC, int nsU, int gridS, int gridC) {
    __shared__ __align__(16) char sA[GROWS * SR2];   // 16 KB

    const bool isC  = blockIdx.x >= (unsigned)gridS;
    const int  tid0 = isC ? (blockIdx.x - gridS) : blockIdx.x;
    const int  tstr = isC ? gridC : gridS;
    const int  nrows = isC ? nC : nS;
    const int  nTiles = (nrows + GROWS - 1) / GROWS;
    const float* ztab = isC ? zc : zs;
    uint32_t*    htab = g_h + (isC ? (size_t)nsU : 0);
    const int kofs = isC ? HID : 0;

    const int tid  = threadIdx.x;
    const int lane = tid & 31;
    const int wid  = tid >> 5;
    const int tq   = lane & 3;
    const int tr   = lane >> 2;
    const int wcol = wid * 32;

    // B = W1 half fragments: built ONCE per persistent CTA (64 regs)
    uint32_t B[4][8][2];
    #pragma unroll
    for (int nb = 0; nb < 4; nb++) {
        const int n = wcol + nb * 8 + tr;
        #pragma unroll
        for (int s = 0; s < 8; s++)
            #pragma unroll
            for (int hh = 0; hh < 2; hh++) {
                const int k0 = kofs + s * 16 + tq * 2 + hh * 8;
                B[nb][s][hh] = hfpair(W1[(size_t)k0 * HID + n],
                                      W1[(size_t)(k0 + 1) * HID + n]);
            }
    }

    const uint32_t ab = smem_u32(sA);
    const int r0  = lane & 15;
    const int hh0 = lane >> 4;

    for (int t = tid0; t < nTiles; t += tstr) {
        const int rbase = t * GROWS;

        // A: fp32 LDG.128 (coalesced) -> cvt -> swizzled fp16 STS
        #pragma unroll
        for (int p = 0; p < 16; p++) {                 // 2048 float4 / 128 threads
            const int i  = tid + p * 128;
            const int r  = i >> 5;
            const int f4 = i & 31;
            int rg = rbase + r; if (rg >= nrows) rg = nrows - 1;
            const float4 v = ((const float4*)(ztab + (size_t)rg * HID))[f4];
            const uint32_t h0 = hfpair(v.x, v.y), h1 = hfpair(v.z, v.w);
            const int c = f4 >> 1, hf = f4 & 1;
            const int cs = (c & 8) | ((c ^ r) & 7);
            *(uint2*)(sA + r * SR2 + cs * 16 + hf * 8) = make_uint2(h0, h1);
        }
        __syncthreads();

        float D[4][4][4];
        #pragma unroll
        for (int mb = 0; mb < 4; mb++)
            #pragma unroll
            for (int nb = 0; nb < 4; nb++)
                #pragma unroll
                for (int i = 0; i < 4; i++) D[mb][nb][i] = 0.f;

        #pragma unroll
        for (int s = 0; s < 8; s++) {
            const int c = 2 * s + hh0;
            uint32_t A[4][4];
            #pragma unroll
            for (int mb = 0; mb < 4; mb++) {
                const int r  = mb * 16 + r0;
                const int cs = (c & 8) | ((c ^ r) & 7);
                ldmat4(A[mb], ab + (uint32_t)(r * SR2 + cs * 16));
            }
            #pragma unroll
            for (int mb = 0; mb < 4; mb++)
                #pragma unroll
                for (int nb = 0; nb < 4; nb++)
                    mma16816(D[mb][nb], A[mb], B[nb][s][0], B[nb][s][1]);
        }

        #pragma unroll
        for (int mb = 0; mb < 4; mb++)
            #pragma unroll
            for (int nb = 0; nb < 4; nb++) {
                const int cp = (wcol >> 1) + nb * 4 + tq;
                const int r1 = rbase + mb * 16 + tr;
                const int r2 = r1 + 8;
                if (r1 < nrows) htab[(size_t)r1 * 64 + cp] = hfpair(D[mb][nb][0], D[mb][nb][1]);
                if (r2 < nrows) htab[(size_t)r2 * 64 + cp] = hfpair(D[mb][nb][2], D[mb][nb][3]);
            }
        __syncthreads();   // all ldsm done before next tile's STS
    }
}

// ---------------- 2) edge pass, unroll x2: out = relu(h_s+h_c+b1).W2 + b2 ----------------
__global__ void __launch_bounds__(256)
edge_out(const int* __restrict__ row, const int* __restrict__ col,
         const float* __restrict__ b1f, const float* __restrict__ W2f,
         const float* __restrict__ b2f, float* __restrict__ out, int E, int nsU) {
    const int tid = threadIdx.x;
    const int q   = tid & 7;

    __half2 b1h[8];
    float   w2[16];
    #pragma unroll
    for (int j = 0; j < 4; j++) {
        const int c = 8 * q + 2 * j;
        b1h[j]     = __floats2half2_rn(b1f[c],      b1f[c + 1]);
        b1h[4 + j] = __floats2half2_rn(b1f[64 + c], b1f[64 + c + 1]);
    }
    #pragma unroll
    for (int j = 0; j < 8; j++) {
        w2[j]     = W2f[8 * q + j];
        w2[8 + j] = W2f[64 + 8 * q + j];
    }
    const float b2v = b2f[0];
    const __half2 zero = __float2half2_rn(0.f);
    const uint32_t* hS = g_h;
    const uint32_t* hC = g_h + (size_t)nsU;

    const int slot  = (blockIdx.x * blockDim.x + tid) >> 3;
    const int nslot = (gridDim.x * blockDim.x) >> 3;

    for (int eg = slot; eg < E; eg += 2 * nslot) {
        const int eg2   = eg + nslot;
        const bool has2 = eg2 < E;

        const int ri  = row[eg];
        const int ci  = col[eg];
        const int ri2 = has2 ? row[eg2] : ri;
        const int ci2 = has2 ? col[eg2] : ci;

        const uint4* hs  = (const uint4*)(hS + (size_t)ri  * 64);
        const uint4* hc  = (const uint4*)(hC + (size_t)ci  * 64);
        const uint4* hs2 = (const uint4*)(hS + (size_t)ri2 * 64);
        const uint4* hc2 = (const uint4*)(hC + (size_t)ci2 * 64);
        uint4 a0 = hs[q],  a1 = hs[q + 8],  b0 = hc[q],  b1u = hc[q + 8];
        uint4 c0 = hs2[q], c1 = hs2[q + 8], d0 = hc2[q], d1 = hc2[q + 8];

        float acc1 = 0.f, acc2 = 0.f;
        const uint32_t* pa0 = &a0.x; const uint32_t* pb0 = &b0.x;
        const uint32_t* pa1 = &a1.x; const uint32_t* pb1 = &b1u.x;
        const uint32_t* pc0 = &c0.x; const uint32_t* pd0 = &d0.x;
        const uint32_t* pc1 = &c1.x; const uint32_t* pd1 = &d1.x;
        #pragma unroll
        for (int i = 0; i < 4; i++) {
            __half2 h1 = __hmax2(__hadd2(__hadd2(*(const __half2*)&pa0[i],
                                                 *(const __half2*)&pb0[i]), b1h[i]), zero);
            __half2 h2 = __hmax2(__hadd2(__hadd2(*(const __half2*)&pa1[i],
                                                 *(const __half2*)&pb1[i]), b1h[4 + i]), zero);
            float2 f1 = __half22float2(h1);
            float2 f2 = __half22float2(h2);
            acc1 = fmaf(f1.x, w2[2 * i], acc1);
            acc1 = fmaf(f1.y, w2[2 * i + 1], acc1);
            acc1 = fmaf(f2.x, w2[8 + 2 * i], acc1);
            acc1 = fmaf(f2.y, w2[8 + 2 * i + 1], acc1);

            __half2 g1 = __hmax2(__hadd2(__hadd2(*(const __half2*)&pc0[i],
                                                 *(const __half2*)&pd0[i]), b1h[i]), zero);
            __half2 g2 = __hmax2(__hadd2(__hadd2(*(const __half2*)&pc1[i],
                                                 *(const __half2*)&pd1[i]), b1h[4 + i]), zero);
            float2 e1 = __half22float2(g1);
            float2 e2 = __half22float2(g2);
            acc2 = fmaf(e1.x, w2[2 * i], acc2);
            acc2 = fmaf(e1.y, w2[2 * i + 1], acc2);
            acc2 = fmaf(e2.x, w2[8 + 2 * i], acc2);
            acc2 = fmaf(e2.y, w2[8 + 2 * i + 1], acc2);
        }
        #pragma unroll
        for (int m = 1; m <= 4; m <<= 1) {
            acc1 += __shfl_xor_sync(0xffffffffu, acc1, m);
            acc2 += __shfl_xor_sync(0xffffffffu, acc2, m);
        }
        if (q == 0) {
            out[eg] = acc1 + b2v;
            if (has2) out[eg2] = acc2 + b2v;
        }
    }
}

extern "C" void kernel_launch(void* const* d_in, const int* in_sizes, int n_in,
                              void* d_out, int out_size)
{
    const float* zs  = (const float*)d_in[0];
    const float* zc  = (const float*)d_in[1];
    const int*   row = (const int*)d_in[2];
    const int*   col = (const int*)d_in[3];
    const float* W1  = (const float*)d_in[4];
    const float* b1  = (const float*)d_in[5];
    const float* W2  = (const float*)d_in[6];
    const float* b2  = (const float*)d_in[7];
    float* out = (float*)d_out;

    const int E  = in_sizes[2];
    const int nS = in_sizes[0] / HID;
    const int nC = in_sizes[1] / HID;
    const int nsU = nS * 64;

    int sms = 148;
    cudaDeviceGetAttribute(&sms, cudaDevAttrMultiProcessorCount, 0);

    // 1) persistent per-node GEMM: role-split grid (proportional to row counts)
    const int gridTot = 3 * sms;
    long long tot = (long long)nS + nC;
    int gridS = (int)((long long)gridTot * nS / tot);
    if (gridS < 1) gridS = 1;
    if (gridS > gridTot - 1) gridS = gridTot - 1;
    const int gridC = gridTot - gridS;
    gemm_pre<<<gridTot, 128>>>(zs, zc, W1, nS, nC, nsU, gridS, gridC);

    // 2) edge pass
    edge_out<<<8 * sms, 256>>>(row, col, b1, W2, b2, out, E, nsU);
}